// round 14
// baseline (speedup 1.0000x reference)
#include <cuda_runtime.h>
#include <cuda_fp16.h>

#define NN 100000
#define EE 1200000
#define GG 1000
#define HH 64
#define FIN 7
#define GFD 10
#define TT 5
#define SCAN_B 250
#define SCAN_R 400   // NN / SCAN_B exactly

// ---------------- scratch (static device globals; no allocation) -------------
__device__ int    g_cnt[NN];
__device__ int    g_wp[NN];
__device__ int    g_ptr[NN + 1];
__device__ float  g_dis[NN];
__device__ int2   g_epack[EE];          // {src, bitcast(norm)}
__device__ __align__(256) float  g_ax[NN * 8];
__device__ __align__(256) __half g_h16[NN * HH];   // fp16 activations (gathered)
__device__ __align__(256) float  g_agg[NN * HH];
__device__ float g_bnsum[HH];
__device__ float g_bnsq[HH];
__device__ float g_aff_a[HH];
__device__ float g_aff_c[HH];
__device__ int   g_gcnt[GG];
__device__ int   g_goff[GG + 1];
__device__ int   g_bsum[SCAN_B];

// ---------------- f32x2 packed helpers --------------------------------------
__device__ __forceinline__ unsigned long long pack2(float a, float b) {
    unsigned long long r;
    asm("mov.b64 %0, {%1, %2};" : "=l"(r) : "f"(a), "f"(b));
    return r;
}
__device__ __forceinline__ unsigned long long fma2(unsigned long long a,
                                                   unsigned long long b,
                                                   unsigned long long c) {
    unsigned long long d;
    asm("fma.rn.f32x2 %0, %1, %2, %3;" : "=l"(d) : "l"(a), "l"(b), "l"(c));
    return d;
}
__device__ __forceinline__ float2 unpack2(unsigned long long v) {
    float2 f;
    asm("mov.b64 {%0, %1}, %2;" : "=f"(f.x), "=f"(f.y) : "l"(v));
    return f;
}

// ---------------- preprocessing --------------------------------------------
__global__ void k_init() {
    int i = blockIdx.x * blockDim.x + threadIdx.x;
    int stride = gridDim.x * blockDim.x;
    for (int j = i; j < NN; j += stride) g_cnt[j] = 0;
    if (i < GG) g_gcnt[i] = 0;
    if (i < HH) { g_bnsum[i] = 0.f; g_bnsq[i] = 0.f; }
}

// 2 edges (and 2 batch entries) per thread via int2 loads
__global__ void k_hist(const int* __restrict__ ei,
                       const int* __restrict__ batch) {
    int i = (blockIdx.x * blockDim.x + threadIdx.x) * 2;
    if (i < EE) {   // EE even -> i+1 valid whenever i valid
        int2 d = *(const int2*)(ei + EE + i);
        atomicAdd(&g_cnt[d.x], 1);
        atomicAdd(&g_cnt[d.y], 1);
    }
    if (i + 1 < NN) {
        int2 b = *(const int2*)(batch + i);
        atomicAdd(&g_gcnt[b.x], 1);
        atomicAdd(&g_gcnt[b.y], 1);
    } else if (i < NN) {
        atomicAdd(&g_gcnt[batch[i]], 1);
    }
}

// per-block reduce of g_cnt (for scan) + compute g_dis in the same pass
__global__ void k_scan1() {
    __shared__ int sh[256];
    int b = blockIdx.x;
    int lo = b * SCAN_R, hi = lo + SCAN_R;
    int s = 0;
    for (int j = lo + threadIdx.x; j < hi; j += 256) {
        int c = g_cnt[j];
        s += c;
        g_dis[j] = rsqrtf((float)(c + 1));   // deg incl self loop
    }
    sh[threadIdx.x] = s; __syncthreads();
    for (int off = 128; off > 0; off >>= 1) {
        if (threadIdx.x < off) sh[threadIdx.x] += sh[threadIdx.x + off];
        __syncthreads();
    }
    if (threadIdx.x == 0) g_bsum[b] = sh[0];
}

// block 0: exclusive scan of g_bsum; block 1: exclusive scan of g_gcnt -> g_goff
__global__ void k_scan2g() {
    __shared__ int sh[1024];
    int t = threadIdx.x;
    int v;
    if (blockIdx.x == 0) v = (t < SCAN_B) ? g_bsum[t] : 0;
    else                 v = (t < GG)     ? g_gcnt[t] : 0;
    sh[t] = v; __syncthreads();
    for (int off = 1; off < 1024; off <<= 1) {
        int u = (t >= off) ? sh[t - off] : 0;
        __syncthreads();
        sh[t] += u;
        __syncthreads();
    }
    if (blockIdx.x == 0) {
        if (t < SCAN_B) g_bsum[t] = sh[t] - v;
    } else {
        if (t < GG) g_goff[t] = sh[t] - v;
        if (t == 0) g_goff[GG] = NN;
    }
}

// 512 threads, one 400-element tile per block, shuffle-based scan
__global__ void __launch_bounds__(512) k_scan3() {
    int b = blockIdx.x, t = threadIdx.x;
    int idx = b * SCAN_R + t;
    int v = (t < SCAN_R) ? g_cnt[idx] : 0;
    int lane = t & 31, wid = t >> 5;
    int x = v;
#pragma unroll
    for (int o = 1; o < 32; o <<= 1) {
        int y = __shfl_up_sync(0xffffffffu, x, o);
        if (lane >= o) x += y;
    }
    __shared__ int wsum[16];
    if (lane == 31) wsum[wid] = x;
    __syncthreads();
    if (t < 16) {
        int y = wsum[t];
#pragma unroll
        for (int o = 1; o < 16; o <<= 1) {
            int z = __shfl_up_sync(0xffffu, y, o);
            if (t >= o) y += z;
        }
        wsum[t] = y;
    }
    __syncthreads();
    int ex = g_bsum[b] + x - v + (wid ? wsum[wid - 1] : 0);
    if (t < SCAN_R) { g_ptr[idx] = ex; g_wp[idx] = ex; }
    if (b == SCAN_B - 1 && t == 0) g_ptr[NN] = EE;
}

// 2 edges per thread
__global__ void k_scatter(const int* __restrict__ ei) {
    int i = (blockIdx.x * blockDim.x + threadIdx.x) * 2;
    if (i >= EE) return;   // EE even -> both lanes valid
    int2 s2 = *(const int2*)(ei + i);
    int2 d2 = *(const int2*)(ei + EE + i);
    float ds0 = g_dis[s2.x], dd0 = g_dis[d2.x];
    float ds1 = g_dis[s2.y], dd1 = g_dis[d2.y];
    int pos0 = atomicAdd(&g_wp[d2.x], 1);
    int2 p0; p0.x = s2.x; p0.y = __float_as_int(ds0 * dd0);
    g_epack[pos0] = p0;
    int pos1 = atomicAdd(&g_wp[d2.y], 1);
    int2 p1; p1.x = s2.y; p1.y = __float_as_int(ds1 * dd1);
    g_epack[pos1] = p1;
}

// ---------------- layer 1: aggregate raw x (7 dims), 8 lanes per node -------
__global__ void k_aggx(const float* __restrict__ x) {
    int t = blockIdx.x * 256 + threadIdx.x;
    int node = t >> 3;
    int sl = t & 7;
    if (node >= NN) return;
    float di = g_dis[node];
    float xv = (sl < FIN) ? x[node * FIN + sl] : 0.f;
    float acc = xv * di * di;   // self loop, norm = 1/deg
    int e0 = g_ptr[node], e1 = g_ptr[node + 1];
    for (int e = e0; e < e1; e++) {
        int2 ep = g_epack[e];
        float w = __int_as_float(ep.y);
        float v = (sl < FIN) ? x[ep.x * FIN + sl] : 0.f;
        acc = fmaf(w, v, acc);
    }
    if (sl < FIN) g_ax[node * 8 + sl] = acc;
}

// h = ax @ W1 + b1 (N x 7 @ 7 x 64), writes fp16 g_h16, fused BN-stat accum
__global__ void __launch_bounds__(256) k_gemm1(const float* __restrict__ W1,
                                               const float* __restrict__ b1) {
    __shared__ float Ws[FIN * HH];
    __shared__ float bs[HH];
    __shared__ float red[2][16][HH];   // 8 KB
    int t = threadIdx.x;
    for (int j = t; j < FIN * HH; j += 256) Ws[j] = W1[j];
    if (t < HH) bs[t] = b1[t];
    __syncthreads();
    int nl = t >> 4;
    int n  = blockIdx.x * 16 + nl;     // always < NN (NN % 16 == 0)
    int c4 = (t & 15) * 4;
    float a[FIN];
#pragma unroll
    for (int k = 0; k < FIN; k++) a[k] = g_ax[n * 8 + k];
    float acc0 = bs[c4], acc1 = bs[c4 + 1], acc2 = bs[c4 + 2], acc3 = bs[c4 + 3];
#pragma unroll
    for (int k = 0; k < FIN; k++) {
        float hk = a[k];
        const float* wr = &Ws[k * HH + c4];
        acc0 = fmaf(hk, wr[0], acc0);
        acc1 = fmaf(hk, wr[1], acc1);
        acc2 = fmaf(hk, wr[2], acc2);
        acc3 = fmaf(hk, wr[3], acc3);
    }
    __half2 p01 = __floats2half2_rn(acc0, acc1);
    __half2 p23 = __floats2half2_rn(acc2, acc3);
    __half2* dst = (__half2*)(g_h16 + (size_t)n * HH);
    dst[(t & 15) * 2]     = p01;
    dst[(t & 15) * 2 + 1] = p23;
    red[0][nl][c4]     = acc0;           red[1][nl][c4]     = acc0 * acc0;
    red[0][nl][c4 + 1] = acc1;           red[1][nl][c4 + 1] = acc1 * acc1;
    red[0][nl][c4 + 2] = acc2;           red[1][nl][c4 + 2] = acc2 * acc2;
    red[0][nl][c4 + 3] = acc3;           red[1][nl][c4 + 3] = acc3 * acc3;
    __syncthreads();
    if (t < 128) {
        int w = t >> 6, col = t & 63;
        float s = 0.f;
#pragma unroll
        for (int r = 0; r < 16; r++) s += red[w][r][col];
        atomicAdd(w ? &g_bnsq[col] : &g_bnsum[col], s);
    }
}

__global__ void k_bnfin(const float* __restrict__ gamma, const float* __restrict__ beta) {
    int t = threadIdx.x;  // 64 threads
    float mean = g_bnsum[t] * (1.f / (float)NN);
    float var  = g_bnsq[t] * (1.f / (float)NN) - mean * mean;
    float rstd = rsqrtf(var + 1e-5f);
    float a = gamma[t] * rstd;
    g_aff_a[t] = a;
    g_aff_c[t] = beta[t] - mean * a;
    g_bnsum[t] = 0.f;  // ready for next BN
    g_bnsq[t]  = 0.f;
}

// ---------------- H=64 aggregation: g_agg = A_norm @ relu(bn(h16)) ----------
// warp per node, lane owns 2 columns (half2 load), 2-edge unroll for MLP
__global__ void __launch_bounds__(256) k_agg() {
    int node = blockIdx.x * 8 + (threadIdx.x >> 5);
    int lane = threadIdx.x & 31;
    if (node >= NN) return;
    float a0 = g_aff_a[2 * lane],     a1 = g_aff_a[2 * lane + 1];
    float c0 = g_aff_c[2 * lane],     c1 = g_aff_c[2 * lane + 1];
    float di = g_dis[node];
    float invd = di * di;
    float2 hv = __half22float2(((const __half2*)(g_h16 + (size_t)node * HH))[lane]);
    float acc0 = fmaxf(fmaf(a0, hv.x, c0), 0.f) * invd;
    float acc1 = fmaxf(fmaf(a1, hv.y, c1), 0.f) * invd;
    int e0 = g_ptr[node], e1 = g_ptr[node + 1];
    int e = e0;
    for (; e + 2 <= e1; e += 2) {
        int2 ea = g_epack[e];
        int2 eb = g_epack[e + 1];
        float w0 = __int_as_float(ea.y);
        float w1 = __int_as_float(eb.y);
        float2 p = __half22float2(((const __half2*)(g_h16 + (size_t)ea.x * HH))[lane]);
        float2 q = __half22float2(((const __half2*)(g_h16 + (size_t)eb.x * HH))[lane]);
        acc0 = fmaf(w0, fmaxf(fmaf(a0, p.x, c0), 0.f), acc0);
        acc1 = fmaf(w0, fmaxf(fmaf(a1, p.y, c1), 0.f), acc1);
        acc0 = fmaf(w1, fmaxf(fmaf(a0, q.x, c0), 0.f), acc0);
        acc1 = fmaf(w1, fmaxf(fmaf(a1, q.y, c1), 0.f), acc1);
    }
    if (e < e1) {
        int2 ea = g_epack[e];
        float w0 = __int_as_float(ea.y);
        float2 p = __half22float2(((const __half2*)(g_h16 + (size_t)ea.x * HH))[lane]);
        acc0 = fmaf(w0, fmaxf(fmaf(a0, p.x, c0), 0.f), acc0);
        acc1 = fmaf(w0, fmaxf(fmaf(a1, p.y, c1), 0.f), acc1);
    }
    ((float2*)(g_agg + (size_t)node * HH))[lane] = make_float2(acc0, acc1);
}

// ---------------- h16 = g_agg @ W + b (N x 64 @ 64 x 64), 128 rows/block ----
// f32x2 packed FMA over row pairs; hs2 stored k-major so pairs load as LDS.64
__global__ void __launch_bounds__(256) k_gemm64(const float* __restrict__ W,
                                                const float* __restrict__ b) {
    __shared__ float4 Ws[64 * 16];    // 16 KB  [k][cg]
    __shared__ float2 hs2[64 * 64];   // 32 KB  [k][rowpair]
    int t = threadIdx.x;
    int nb = blockIdx.x * 128;
    for (int j = t; j < 1024; j += 256) Ws[j] = ((const float4*)W)[j];
    {
        int rp = t & 63;              // row pair 0..63
        int kq = t >> 6;              // 0..3
        int r0 = nb + 2 * rp, r1 = r0 + 1;
        const float4* src = (const float4*)g_agg;
#pragma unroll
        for (int c = 0; c < 4; c++) {
            int k4 = kq * 4 + c;      // 0..15
            float4 va = (r0 < NN) ? src[(size_t)r0 * 16 + k4] : make_float4(0.f, 0.f, 0.f, 0.f);
            float4 vb = (r1 < NN) ? src[(size_t)r1 * 16 + k4] : make_float4(0.f, 0.f, 0.f, 0.f);
            hs2[(k4 * 4 + 0) * 64 + rp] = make_float2(va.x, vb.x);
            hs2[(k4 * 4 + 1) * 64 + rp] = make_float2(va.y, vb.y);
            hs2[(k4 * 4 + 2) * 64 + rp] = make_float2(va.z, vb.z);
            hs2[(k4 * 4 + 3) * 64 + rp] = make_float2(va.w, vb.w);
        }
    }
    __syncthreads();
    int cg  = t & 15;     // col group (4 cols)
    int rpg = t >> 4;     // row-pair group (4 pairs = 8 rows)
    float4 bias = ((const float4*)b)[cg];
    unsigned long long accp[4][4];
#pragma unroll
    for (int p = 0; p < 4; p++) {
        accp[p][0] = pack2(bias.x, bias.x);
        accp[p][1] = pack2(bias.y, bias.y);
        accp[p][2] = pack2(bias.z, bias.z);
        accp[p][3] = pack2(bias.w, bias.w);
    }
#pragma unroll 4
    for (int k = 0; k < 64; k++) {
        float4 w = Ws[k * 16 + cg];
        unsigned long long wx = pack2(w.x, w.x);
        unsigned long long wy = pack2(w.y, w.y);
        unsigned long long wz = pack2(w.z, w.z);
        unsigned long long ww = pack2(w.w, w.w);
#pragma unroll
        for (int p = 0; p < 4; p++) {
            float2 hp = hs2[k * 64 + rpg * 4 + p];
            unsigned long long h2 = pack2(hp.x, hp.y);
            accp[p][0] = fma2(h2, wx, accp[p][0]);
            accp[p][1] = fma2(h2, wy, accp[p][1]);
            accp[p][2] = fma2(h2, wz, accp[p][2]);
            accp[p][3] = fma2(h2, ww, accp[p][3]);
        }
    }
    float4 s4 = make_float4(0.f, 0.f, 0.f, 0.f);
    float4 q4 = make_float4(0.f, 0.f, 0.f, 0.f);
#pragma unroll
    for (int p = 0; p < 4; p++) {
        float2 c0 = unpack2(accp[p][0]);
        float2 c1 = unpack2(accp[p][1]);
        float2 c2 = unpack2(accp[p][2]);
        float2 c3 = unpack2(accp[p][3]);
        int r0 = nb + (rpg * 4 + p) * 2;
        int r1 = r0 + 1;
        if (r0 < NN) {
            __half2* dst = (__half2*)(g_h16 + (size_t)r0 * HH);
            dst[cg * 2]     = __floats2half2_rn(c0.x, c1.x);
            dst[cg * 2 + 1] = __floats2half2_rn(c2.x, c3.x);
            s4.x += c0.x; s4.y += c1.x; s4.z += c2.x; s4.w += c3.x;
            q4.x = fmaf(c0.x, c0.x, q4.x); q4.y = fmaf(c1.x, c1.x, q4.y);
            q4.z = fmaf(c2.x, c2.x, q4.z); q4.w = fmaf(c3.x, c3.x, q4.w);
        }
        if (r1 < NN) {
            __half2* dst = (__half2*)(g_h16 + (size_t)r1 * HH);
            dst[cg * 2]     = __floats2half2_rn(c0.y, c1.y);
            dst[cg * 2 + 1] = __floats2half2_rn(c2.y, c3.y);
            s4.x += c0.y; s4.y += c1.y; s4.z += c2.y; s4.w += c3.y;
            q4.x = fmaf(c0.y, c0.y, q4.x); q4.y = fmaf(c1.y, c1.y, q4.y);
            q4.z = fmaf(c2.y, c2.y, q4.z); q4.w = fmaf(c3.y, c3.y, q4.w);
        }
    }
    __syncthreads();
    float4* red = (float4*)Ws;    // reuse W smem (needs 512 float4, has 1024)
    red[(t >> 4) * 16 + cg]       = s4;
    red[256 + (t >> 4) * 16 + cg] = q4;
    __syncthreads();
    if (t < 32) {
        int which = t >> 4, col = t & 15;
        float4 s = make_float4(0.f, 0.f, 0.f, 0.f);
#pragma unroll
        for (int r = 0; r < 16; r++) {
            float4 v = red[which * 256 + r * 16 + col];
            s.x += v.x; s.y += v.y; s.z += v.z; s.w += v.w;
        }
        float* dst = which ? g_bnsq : g_bnsum;
        atomicAdd(&dst[col * 4 + 0], s.x);
        atomicAdd(&dst[col * 4 + 1], s.y);
        atomicAdd(&dst[col * 4 + 2], s.z);
        atomicAdd(&dst[col * 4 + 3], s.w);
    }
}

// ---------------- pooling (over g_agg) + folded W3 + head -------------------
// pooled_h3 = mean(agg) @ W3 + b3  (GEMM-pool commute: pooling is linear)
__global__ void __launch_bounds__(256) k_final(
        const float* __restrict__ gf,  const float* __restrict__ Wg,
        const float* __restrict__ bg,  const float* __restrict__ W3,
        const float* __restrict__ b3,  const float* __restrict__ Wp1,
        const float* __restrict__ bp1, const float* __restrict__ Wp2,
        const float* __restrict__ bp2, float* __restrict__ out) {
    int g = blockIdx.x, t = threadIdx.x;
    int col = t & 63, rg = t >> 6;
    __shared__ float part[4][64];
    __shared__ float pool[64];
    __shared__ float comb[96];
    __shared__ float ys[64];
    int r0 = g_goff[g], r1 = g_goff[g + 1];
    float s = 0.f;
    for (int r = r0 + rg; r < r1; r += 4) s += g_agg[(size_t)r * HH + col];
    part[rg][col] = s;
    __syncthreads();
    if (t < 64) {
        float tot = part[0][t] + part[1][t] + part[2][t] + part[3][t];
        float cntf = (float)(r1 - r0);
        pool[t] = tot / fmaxf(cntf, 1.f);
    } else if (t < 96) {
        int j = t - 64;
        float a = bg[j];
#pragma unroll
        for (int k = 0; k < GFD; k++) a = fmaf(gf[g * GFD + k], Wg[k * 32 + j], a);
        comb[64 + j] = fmaxf(a, 0.f);
    }
    __syncthreads();
    if (t < 64) {
        float y = b3[t];
#pragma unroll
        for (int k = 0; k < HH; k++) y = fmaf(pool[k], W3[k * HH + t], y);
        comb[t] = y;   // no activation on layer-3 output
    }
    __syncthreads();
    if (t < 64) {
        float y = bp1[t];
#pragma unroll
        for (int k = 0; k < 96; k++) y = fmaf(comb[k], Wp1[k * HH + t], y);
        ys[t] = fmaxf(y, 0.f);
    }
    __syncthreads();
    if (t < TT) {
        float o = bp2[t];
#pragma unroll
        for (int k = 0; k < HH; k++) o = fmaf(ys[k], Wp2[k * TT + t], o);
        out[g * TT + t] = o;
    }
}

// ---------------- launch ----------------------------------------------------
extern "C" void kernel_launch(void* const* d_in, const int* in_sizes, int n_in,
                              void* d_out, int out_size) {
    const float* x      = (const float*)d_in[0];
    const float* gfeat  = (const float*)d_in[1];
    const float* W1     = (const float*)d_in[2];
    const float* b1     = (const float*)d_in[3];
    const float* W2     = (const float*)d_in[4];
    const float* b2     = (const float*)d_in[5];
    const float* W3     = (const float*)d_in[6];
    const float* b3     = (const float*)d_in[7];
    const float* gamma1 = (const float*)d_in[8];
    const float* beta1  = (const float*)d_in[9];
    const float* gamma2 = (const float*)d_in[10];
    const float* beta2  = (const float*)d_in[11];
    const float* Wg     = (const float*)d_in[12];
    const float* bg     = (const float*)d_in[13];
    const float* Wp1    = (const float*)d_in[14];
    const float* bp1    = (const float*)d_in[15];
    const float* Wp2    = (const float*)d_in[16];
    const float* bp2    = (const float*)d_in[17];
    const int* ei       = (const int*)d_in[18];
    const int* batch    = (const int*)d_in[19];
    float* out = (float*)d_out;

    const int TB = 256;
    const int gridN  = (NN + TB - 1) / TB;        // 391
    const int gridE2 = (EE / 2 + TB - 1) / TB;    // 2344
    const int gridG64 = (NN + 127) / 128;         // 782

    // preprocessing: degree + dis, CSR, graph offsets
    k_init<<<gridN, TB>>>();
    k_hist<<<gridE2, TB>>>(ei, batch);
    k_scan1<<<SCAN_B, TB>>>();
    k_scan2g<<<2, 1024>>>();
    k_scan3<<<SCAN_B, 512>>>();
    k_scatter<<<gridE2, TB>>>(ei);

    // layer 1: aggregate raw x, then GEMM (A@X)@W1 with fused BN stats
    k_aggx<<<(NN * 8 + TB - 1) / TB, TB>>>(x);
    k_gemm1<<<NN / 16, TB>>>(W1, b1);
    k_bnfin<<<1, 64>>>(gamma1, beta1);

    // layer 2: gather with fused relu(bn(.)), then GEMM with fused BN stats
    k_agg<<<NN / 8, TB>>>();
    k_gemm64<<<gridG64, TB>>>(W2, b2);
    k_bnfin<<<1, 64>>>(gamma2, beta2);

    // layer 3: gather only; GEMM3 folded into k_final (pool-GEMM commute)
    k_agg<<<NN / 8, TB>>>();

    // pooling + folded W3 + MLP head
    k_final<<<GG, TB>>>(gfeat, Wg, bg, W3, b3, Wp1, bp1, Wp2, bp2, out);
}

// round 16
// speedup vs baseline: 1.4199x; 1.4199x over previous
#include <cuda_runtime.h>
#include <cuda_fp16.h>

#define NN 100000
#define EE 1200000
#define GG 1000
#define HH 64
#define FIN 7
#define GFD 10
#define TT 5
#define SCAN_B 250
#define SCAN_R 400   // NN / SCAN_B exactly

// ---------------- scratch (static device globals; no allocation) -------------
__device__ int    g_cnt[NN];
__device__ int    g_wp[NN];
__device__ int    g_ptr[NN + 1];
__device__ float  g_dis[NN];
__device__ int2   g_epack[EE];          // {src, bitcast(norm)}
__device__ __align__(256) float  g_ax[NN * 8];
__device__ __align__(256) __half g_h16[NN * HH];   // fp16 activations (gathered)
__device__ __align__(256) float  g_agg[NN * HH];
__device__ float g_bnsum[HH];
__device__ float g_bnsq[HH];
__device__ float g_aff_a[HH];
__device__ float g_aff_c[HH];
__device__ int   g_gcnt[GG];
__device__ int   g_goff[GG + 1];
__device__ int   g_bsum[SCAN_B];

// ---------------- f32x2 packed helpers --------------------------------------
__device__ __forceinline__ unsigned long long pack2(float a, float b) {
    unsigned long long r;
    asm("mov.b64 %0, {%1, %2};" : "=l"(r) : "f"(a), "f"(b));
    return r;
}
__device__ __forceinline__ unsigned long long fma2(unsigned long long a,
                                                   unsigned long long b,
                                                   unsigned long long c) {
    unsigned long long d;
    asm("fma.rn.f32x2 %0, %1, %2, %3;" : "=l"(d) : "l"(a), "l"(b), "l"(c));
    return d;
}
__device__ __forceinline__ float2 unpack2(unsigned long long v) {
    float2 f;
    asm("mov.b64 {%0, %1}, %2;" : "=f"(f.x), "=f"(f.y) : "l"(v));
    return f;
}

// ---------------- preprocessing --------------------------------------------
__global__ void k_init() {
    int i = blockIdx.x * blockDim.x + threadIdx.x;
    int stride = gridDim.x * blockDim.x;
    for (int j = i; j < NN; j += stride) g_cnt[j] = 0;
    if (i < GG) g_gcnt[i] = 0;
    if (i < HH) { g_bnsum[i] = 0.f; g_bnsq[i] = 0.f; }
}

__global__ void k_hist(const int* __restrict__ ei,
                       const int* __restrict__ batch) {
    int i = blockIdx.x * blockDim.x + threadIdx.x;
    if (i < EE) atomicAdd(&g_cnt[ei[EE + i]], 1);
    if (i < NN) atomicAdd(&g_gcnt[batch[i]], 1);
}

// per-block reduce of g_cnt (for scan) + compute g_dis in the same pass
__global__ void k_scan1() {
    __shared__ int sh[256];
    int b = blockIdx.x;
    int lo = b * SCAN_R, hi = lo + SCAN_R;
    int s = 0;
    for (int j = lo + threadIdx.x; j < hi; j += 256) {
        int c = g_cnt[j];
        s += c;
        g_dis[j] = rsqrtf((float)(c + 1));   // deg incl self loop
    }
    sh[threadIdx.x] = s; __syncthreads();
    for (int off = 128; off > 0; off >>= 1) {
        if (threadIdx.x < off) sh[threadIdx.x] += sh[threadIdx.x + off];
        __syncthreads();
    }
    if (threadIdx.x == 0) g_bsum[b] = sh[0];
}

// block 0: exclusive scan of g_bsum; block 1: exclusive scan of g_gcnt -> g_goff
__global__ void k_scan2g() {
    __shared__ int sh[1024];
    int t = threadIdx.x;
    int v;
    if (blockIdx.x == 0) v = (t < SCAN_B) ? g_bsum[t] : 0;
    else                 v = (t < GG)     ? g_gcnt[t] : 0;
    sh[t] = v; __syncthreads();
    for (int off = 1; off < 1024; off <<= 1) {
        int u = (t >= off) ? sh[t - off] : 0;
        __syncthreads();
        sh[t] += u;
        __syncthreads();
    }
    if (blockIdx.x == 0) {
        if (t < SCAN_B) g_bsum[t] = sh[t] - v;
    } else {
        if (t < GG) g_goff[t] = sh[t] - v;
        if (t == 0) g_goff[GG] = NN;
    }
}

__global__ void k_scan3() {
    __shared__ int sh[256];
    int b = blockIdx.x, t = threadIdx.x;
    int lo = b * SCAN_R, hi = lo + SCAN_R;
    int carry = g_bsum[b];
    for (int base = lo; base < hi; base += 256) {
        int idx = base + t;
        int v = (idx < hi) ? g_cnt[idx] : 0;
        sh[t] = v; __syncthreads();
        for (int off = 1; off < 256; off <<= 1) {
            int u = (t >= off) ? sh[t - off] : 0;
            __syncthreads();
            sh[t] += u;
            __syncthreads();
        }
        if (idx < hi) {
            int ex = carry + sh[t] - v;
            g_ptr[idx] = ex;
            g_wp[idx]  = ex;
        }
        carry += sh[255];
        __syncthreads();
    }
    if (b == SCAN_B - 1 && t == 0) g_ptr[NN] = EE;
}

__global__ void k_scatter(const int* __restrict__ ei) {
    int i = blockIdx.x * blockDim.x + threadIdx.x;
    if (i >= EE) return;
    int s = ei[i];
    int d = ei[EE + i];
    int pos = atomicAdd(&g_wp[d], 1);
    int2 p;
    p.x = s;
    p.y = __float_as_int(g_dis[s] * g_dis[d]);
    g_epack[pos] = p;
}

// ---------------- layer 1: aggregate raw x (7 dims), 8 lanes per node -------
__global__ void k_aggx(const float* __restrict__ x) {
    int t = blockIdx.x * 256 + threadIdx.x;
    int node = t >> 3;
    int sl = t & 7;
    if (node >= NN) return;
    float di = g_dis[node];
    float xv = (sl < FIN) ? x[node * FIN + sl] : 0.f;
    float acc = xv * di * di;   // self loop, norm = 1/deg
    int e0 = g_ptr[node], e1 = g_ptr[node + 1];
    for (int e = e0; e < e1; e++) {
        int2 ep = g_epack[e];
        float w = __int_as_float(ep.y);
        float v = (sl < FIN) ? x[ep.x * FIN + sl] : 0.f;
        acc = fmaf(w, v, acc);
    }
    if (sl < FIN) g_ax[node * 8 + sl] = acc;
}

// h = ax @ W1 + b1 (N x 7 @ 7 x 64), writes fp16 g_h16, fused BN-stat accum
__global__ void __launch_bounds__(256) k_gemm1(const float* __restrict__ W1,
                                               const float* __restrict__ b1) {
    __shared__ float Ws[FIN * HH];
    __shared__ float bs[HH];
    __shared__ float red[2][16][HH];   // 8 KB
    int t = threadIdx.x;
    for (int j = t; j < FIN * HH; j += 256) Ws[j] = W1[j];
    if (t < HH) bs[t] = b1[t];
    __syncthreads();
    int nl = t >> 4;
    int n  = blockIdx.x * 16 + nl;     // always < NN (NN % 16 == 0)
    int c4 = (t & 15) * 4;
    float a[FIN];
#pragma unroll
    for (int k = 0; k < FIN; k++) a[k] = g_ax[n * 8 + k];
    float acc0 = bs[c4], acc1 = bs[c4 + 1], acc2 = bs[c4 + 2], acc3 = bs[c4 + 3];
#pragma unroll
    for (int k = 0; k < FIN; k++) {
        float hk = a[k];
        const float* wr = &Ws[k * HH + c4];
        acc0 = fmaf(hk, wr[0], acc0);
        acc1 = fmaf(hk, wr[1], acc1);
        acc2 = fmaf(hk, wr[2], acc2);
        acc3 = fmaf(hk, wr[3], acc3);
    }
    __half2 p01 = __floats2half2_rn(acc0, acc1);
    __half2 p23 = __floats2half2_rn(acc2, acc3);
    __half2* dst = (__half2*)(g_h16 + (size_t)n * HH);
    dst[(t & 15) * 2]     = p01;
    dst[(t & 15) * 2 + 1] = p23;
    red[0][nl][c4]     = acc0;           red[1][nl][c4]     = acc0 * acc0;
    red[0][nl][c4 + 1] = acc1;           red[1][nl][c4 + 1] = acc1 * acc1;
    red[0][nl][c4 + 2] = acc2;           red[1][nl][c4 + 2] = acc2 * acc2;
    red[0][nl][c4 + 3] = acc3;           red[1][nl][c4 + 3] = acc3 * acc3;
    __syncthreads();
    if (t < 128) {
        int w = t >> 6, col = t & 63;
        float s = 0.f;
#pragma unroll
        for (int r = 0; r < 16; r++) s += red[w][r][col];
        atomicAdd(w ? &g_bnsq[col] : &g_bnsum[col], s);
    }
}

__global__ void k_bnfin(const float* __restrict__ gamma, const float* __restrict__ beta) {
    int t = threadIdx.x;  // 64 threads
    float mean = g_bnsum[t] * (1.f / (float)NN);
    float var  = g_bnsq[t] * (1.f / (float)NN) - mean * mean;
    float rstd = rsqrtf(var + 1e-5f);
    float a = gamma[t] * rstd;
    g_aff_a[t] = a;
    g_aff_c[t] = beta[t] - mean * a;
    g_bnsum[t] = 0.f;  // ready for next BN
    g_bnsq[t]  = 0.f;
}

// ---------------- H=64 aggregation: g_agg = A_norm @ relu(bn(h16)) ----------
// warp per node, lane owns 2 columns (half2 load), 2-edge unroll for MLP
__global__ void __launch_bounds__(256) k_agg() {
    int node = blockIdx.x * 8 + (threadIdx.x >> 5);
    int lane = threadIdx.x & 31;
    if (node >= NN) return;
    float a0 = g_aff_a[2 * lane],     a1 = g_aff_a[2 * lane + 1];
    float c0 = g_aff_c[2 * lane],     c1 = g_aff_c[2 * lane + 1];
    float di = g_dis[node];
    float invd = di * di;
    float2 hv = __half22float2(((const __half2*)(g_h16 + (size_t)node * HH))[lane]);
    float acc0 = fmaxf(fmaf(a0, hv.x, c0), 0.f) * invd;
    float acc1 = fmaxf(fmaf(a1, hv.y, c1), 0.f) * invd;
    int e0 = g_ptr[node], e1 = g_ptr[node + 1];
    int e = e0;
    for (; e + 2 <= e1; e += 2) {
        int2 ea = g_epack[e];
        int2 eb = g_epack[e + 1];
        float w0 = __int_as_float(ea.y);
        float w1 = __int_as_float(eb.y);
        float2 p = __half22float2(((const __half2*)(g_h16 + (size_t)ea.x * HH))[lane]);
        float2 q = __half22float2(((const __half2*)(g_h16 + (size_t)eb.x * HH))[lane]);
        acc0 = fmaf(w0, fmaxf(fmaf(a0, p.x, c0), 0.f), acc0);
        acc1 = fmaf(w0, fmaxf(fmaf(a1, p.y, c1), 0.f), acc1);
        acc0 = fmaf(w1, fmaxf(fmaf(a0, q.x, c0), 0.f), acc0);
        acc1 = fmaf(w1, fmaxf(fmaf(a1, q.y, c1), 0.f), acc1);
    }
    if (e < e1) {
        int2 ea = g_epack[e];
        float w0 = __int_as_float(ea.y);
        float2 p = __half22float2(((const __half2*)(g_h16 + (size_t)ea.x * HH))[lane]);
        acc0 = fmaf(w0, fmaxf(fmaf(a0, p.x, c0), 0.f), acc0);
        acc1 = fmaf(w0, fmaxf(fmaf(a1, p.y, c1), 0.f), acc1);
    }
    ((float2*)(g_agg + (size_t)node * HH))[lane] = make_float2(acc0, acc1);
}

// ---------------- h16 = g_agg @ W + b (N x 64 @ 64 x 64), 128 rows/block ----
// f32x2 packed FMA over row pairs; hs2 stored k-major so pairs load as LDS.64
__global__ void __launch_bounds__(256) k_gemm64(const float* __restrict__ W,
                                                const float* __restrict__ b) {
    __shared__ float4 Ws[64 * 16];    // 16 KB  [k][cg]
    __shared__ float2 hs2[64 * 64];   // 32 KB  [k][rowpair]
    int t = threadIdx.x;
    int nb = blockIdx.x * 128;
    for (int j = t; j < 1024; j += 256) Ws[j] = ((const float4*)W)[j];
    {
        int rp = t & 63;              // row pair 0..63
        int kq = t >> 6;              // 0..3
        int r0 = nb + 2 * rp, r1 = r0 + 1;
        const float4* src = (const float4*)g_agg;
#pragma unroll
        for (int c = 0; c < 4; c++) {
            int k4 = kq * 4 + c;      // 0..15
            float4 va = (r0 < NN) ? src[(size_t)r0 * 16 + k4] : make_float4(0.f, 0.f, 0.f, 0.f);
            float4 vb = (r1 < NN) ? src[(size_t)r1 * 16 + k4] : make_float4(0.f, 0.f, 0.f, 0.f);
            hs2[(k4 * 4 + 0) * 64 + rp] = make_float2(va.x, vb.x);
            hs2[(k4 * 4 + 1) * 64 + rp] = make_float2(va.y, vb.y);
            hs2[(k4 * 4 + 2) * 64 + rp] = make_float2(va.z, vb.z);
            hs2[(k4 * 4 + 3) * 64 + rp] = make_float2(va.w, vb.w);
        }
    }
    __syncthreads();
    int cg  = t & 15;     // col group (4 cols)
    int rpg = t >> 4;     // row-pair group (4 pairs = 8 rows)
    float4 bias = ((const float4*)b)[cg];
    unsigned long long accp[4][4];
#pragma unroll
    for (int p = 0; p < 4; p++) {
        accp[p][0] = pack2(bias.x, bias.x);
        accp[p][1] = pack2(bias.y, bias.y);
        accp[p][2] = pack2(bias.z, bias.z);
        accp[p][3] = pack2(bias.w, bias.w);
    }
#pragma unroll 4
    for (int k = 0; k < 64; k++) {
        float4 w = Ws[k * 16 + cg];
        unsigned long long wx = pack2(w.x, w.x);
        unsigned long long wy = pack2(w.y, w.y);
        unsigned long long wz = pack2(w.z, w.z);
        unsigned long long ww = pack2(w.w, w.w);
#pragma unroll
        for (int p = 0; p < 4; p++) {
            float2 hp = hs2[k * 64 + rpg * 4 + p];
            unsigned long long h2 = pack2(hp.x, hp.y);
            accp[p][0] = fma2(h2, wx, accp[p][0]);
            accp[p][1] = fma2(h2, wy, accp[p][1]);
            accp[p][2] = fma2(h2, wz, accp[p][2]);
            accp[p][3] = fma2(h2, ww, accp[p][3]);
        }
    }
    float4 s4 = make_float4(0.f, 0.f, 0.f, 0.f);
    float4 q4 = make_float4(0.f, 0.f, 0.f, 0.f);
#pragma unroll
    for (int p = 0; p < 4; p++) {
        float2 c0 = unpack2(accp[p][0]);
        float2 c1 = unpack2(accp[p][1]);
        float2 c2 = unpack2(accp[p][2]);
        float2 c3 = unpack2(accp[p][3]);
        int r0 = nb + (rpg * 4 + p) * 2;
        int r1 = r0 + 1;
        if (r0 < NN) {
            __half2* dst = (__half2*)(g_h16 + (size_t)r0 * HH);
            dst[cg * 2]     = __floats2half2_rn(c0.x, c1.x);
            dst[cg * 2 + 1] = __floats2half2_rn(c2.x, c3.x);
            s4.x += c0.x; s4.y += c1.x; s4.z += c2.x; s4.w += c3.x;
            q4.x = fmaf(c0.x, c0.x, q4.x); q4.y = fmaf(c1.x, c1.x, q4.y);
            q4.z = fmaf(c2.x, c2.x, q4.z); q4.w = fmaf(c3.x, c3.x, q4.w);
        }
        if (r1 < NN) {
            __half2* dst = (__half2*)(g_h16 + (size_t)r1 * HH);
            dst[cg * 2]     = __floats2half2_rn(c0.y, c1.y);
            dst[cg * 2 + 1] = __floats2half2_rn(c2.y, c3.y);
            s4.x += c0.y; s4.y += c1.y; s4.z += c2.y; s4.w += c3.y;
            q4.x = fmaf(c0.y, c0.y, q4.x); q4.y = fmaf(c1.y, c1.y, q4.y);
            q4.z = fmaf(c2.y, c2.y, q4.z); q4.w = fmaf(c3.y, c3.y, q4.w);
        }
    }
    __syncthreads();
    float4* red = (float4*)Ws;    // reuse W smem (needs 512 float4, has 1024)
    red[(t >> 4) * 16 + cg]       = s4;
    red[256 + (t >> 4) * 16 + cg] = q4;
    __syncthreads();
    if (t < 32) {
        int which = t >> 4, col = t & 15;
        float4 s = make_float4(0.f, 0.f, 0.f, 0.f);
#pragma unroll
        for (int r = 0; r < 16; r++) {
            float4 v = red[which * 256 + r * 16 + col];
            s.x += v.x; s.y += v.y; s.z += v.z; s.w += v.w;
        }
        float* dst = which ? g_bnsq : g_bnsum;
        atomicAdd(&dst[col * 4 + 0], s.x);
        atomicAdd(&dst[col * 4 + 1], s.y);
        atomicAdd(&dst[col * 4 + 2], s.z);
        atomicAdd(&dst[col * 4 + 3], s.w);
    }
}

// ---------------- pooling (over g_agg) + folded W3 + head -------------------
// pooled_h3 = mean(agg) @ W3 + b3  (GEMM-pool commute: pooling is linear)
__global__ void __launch_bounds__(256) k_final(
        const float* __restrict__ gf,  const float* __restrict__ Wg,
        const float* __restrict__ bg,  const float* __restrict__ W3,
        const float* __restrict__ b3,  const float* __restrict__ Wp1,
        const float* __restrict__ bp1, const float* __restrict__ Wp2,
        const float* __restrict__ bp2, float* __restrict__ out) {
    int g = blockIdx.x, t = threadIdx.x;
    int col = t & 63, rg = t >> 6;
    __shared__ float part[4][64];
    __shared__ float pool[64];
    __shared__ float comb[96];
    __shared__ float ys[64];
    int r0 = g_goff[g], r1 = g_goff[g + 1];
    float s = 0.f;
    for (int r = r0 + rg; r < r1; r += 4) s += g_agg[(size_t)r * HH + col];
    part[rg][col] = s;
    __syncthreads();
    if (t < 64) {
        float tot = part[0][t] + part[1][t] + part[2][t] + part[3][t];
        float cntf = (float)(r1 - r0);
        pool[t] = tot / fmaxf(cntf, 1.f);
    } else if (t < 96) {
        int j = t - 64;
        float a = bg[j];
#pragma unroll
        for (int k = 0; k < GFD; k++) a = fmaf(gf[g * GFD + k], Wg[k * 32 + j], a);
        comb[64 + j] = fmaxf(a, 0.f);
    }
    __syncthreads();
    if (t < 64) {
        float y = b3[t];
#pragma unroll
        for (int k = 0; k < HH; k++) y = fmaf(pool[k], W3[k * HH + t], y);
        comb[t] = y;   // no activation on layer-3 output
    }
    __syncthreads();
    if (t < 64) {
        float y = bp1[t];
#pragma unroll
        for (int k = 0; k < 96; k++) y = fmaf(comb[k], Wp1[k * HH + t], y);
        ys[t] = fmaxf(y, 0.f);
    }
    __syncthreads();
    if (t < TT) {
        float o = bp2[t];
#pragma unroll
        for (int k = 0; k < HH; k++) o = fmaf(ys[k], Wp2[k * TT + t], o);
        out[g * TT + t] = o;
    }
}

// ---------------- launch ----------------------------------------------------
extern "C" void kernel_launch(void* const* d_in, const int* in_sizes, int n_in,
                              void* d_out, int out_size) {
    const float* x      = (const float*)d_in[0];
    const float* gfeat  = (const float*)d_in[1];
    const float* W1     = (const float*)d_in[2];
    const float* b1     = (const float*)d_in[3];
    const float* W2     = (const float*)d_in[4];
    const float* b2     = (const float*)d_in[5];
    const float* W3     = (const float*)d_in[6];
    const float* b3     = (const float*)d_in[7];
    const float* gamma1 = (const float*)d_in[8];
    const float* beta1  = (const float*)d_in[9];
    const float* gamma2 = (const float*)d_in[10];
    const float* beta2  = (const float*)d_in[11];
    const float* Wg     = (const float*)d_in[12];
    const float* bg     = (const float*)d_in[13];
    const float* Wp1    = (const float*)d_in[14];
    const float* bp1    = (const float*)d_in[15];
    const float* Wp2    = (const float*)d_in[16];
    const float* bp2    = (const float*)d_in[17];
    const int* ei       = (const int*)d_in[18];
    const int* batch    = (const int*)d_in[19];
    float* out = (float*)d_out;

    const int TB = 256;
    const int gridN = (NN + TB - 1) / TB;       // 391
    const int gridE = (EE + TB - 1) / TB;       // 4688
    const int gridG64 = (NN + 127) / 128;       // 782

    // preprocessing: degree + dis, CSR, graph offsets
    k_init<<<gridN, TB>>>();
    k_hist<<<gridE, TB>>>(ei, batch);
    k_scan1<<<SCAN_B, TB>>>();
    k_scan2g<<<2, 1024>>>();
    k_scan3<<<SCAN_B, TB>>>();
    k_scatter<<<gridE, TB>>>(ei);

    // layer 1: aggregate raw x, then GEMM (A@X)@W1 with fused BN stats
    k_aggx<<<(NN * 8 + TB - 1) / TB, TB>>>(x);
    k_gemm1<<<NN / 16, TB>>>(W1, b1);
    k_bnfin<<<1, 64>>>(gamma1, beta1);

    // layer 2: gather with fused relu(bn(.)), then GEMM with fused BN stats
    k_agg<<<NN / 8, TB>>>();
    k_gemm64<<<gridG64, TB>>>(W2, b2);
    k_bnfin<<<1, 64>>>(gamma2, beta2);

    // layer 3: gather only; GEMM3 folded into k_final (pool-GEMM commute)
    k_agg<<<NN / 8, TB>>>();

    // pooling + folded W3 + MLP head
    k_final<<<GG, TB>>>(gfeat, Wg, bg, W3, b3, Wp1, bp1, Wp2, bp2, out);
}

// round 17
// speedup vs baseline: 1.4731x; 1.0374x over previous
#include <cuda_runtime.h>
#include <cuda_fp16.h>

#define NN 100000
#define EE 1200000
#define GG 1000
#define HH 64
#define FIN 7
#define GFD 10
#define TT 5
#define SCAN_B 250
#define SCAN_R 400   // NN / SCAN_B exactly

// ---------------- scratch (static device globals; no allocation) -------------
__device__ int    g_cnt[NN];
__device__ int    g_wp[NN];
__device__ int    g_ptr[NN + 1];
__device__ float  g_dis[NN];
__device__ int2   g_epack[EE];          // {src, bitcast(norm)}
__device__ __align__(256) __half g_h16[NN * HH];   // fp16 activations (gathered)
__device__ __align__(256) float  g_agg[NN * HH];
__device__ float g_bnsum[HH];
__device__ float g_bnsq[HH];
__device__ float g_aff_a[HH];
__device__ float g_aff_c[HH];
__device__ int   g_gcnt[GG];
__device__ int   g_goff[GG + 1];
__device__ int   g_aggr[SCAN_B];
__device__ int   g_flag[SCAN_B];
__device__ int   g_ctr1;
__device__ int   g_ctr2;

// ---------------- f32x2 packed helpers --------------------------------------
__device__ __forceinline__ unsigned long long pack2(float a, float b) {
    unsigned long long r;
    asm("mov.b64 %0, {%1, %2};" : "=l"(r) : "f"(a), "f"(b));
    return r;
}
__device__ __forceinline__ unsigned long long fma2(unsigned long long a,
                                                   unsigned long long b,
                                                   unsigned long long c) {
    unsigned long long d;
    asm("fma.rn.f32x2 %0, %1, %2, %3;" : "=l"(d) : "l"(a), "l"(b), "l"(c));
    return d;
}
__device__ __forceinline__ float2 unpack2(unsigned long long v) {
    float2 f;
    asm("mov.b64 {%0, %1}, %2;" : "=f"(f.x), "=f"(f.y) : "l"(v));
    return f;
}

// ---------------- preprocessing --------------------------------------------
__global__ void k_init() {
    int i = blockIdx.x * blockDim.x + threadIdx.x;
    int stride = gridDim.x * blockDim.x;
    for (int j = i; j < NN; j += stride) g_cnt[j] = 0;
    if (i < GG) g_gcnt[i] = 0;
    if (i < SCAN_B) g_flag[i] = 0;
    if (i < HH) { g_bnsum[i] = 0.f; g_bnsq[i] = 0.f; }
    if (i == 0) { g_ctr1 = 0; g_ctr2 = 0; }
}

__global__ void k_hist(const int* __restrict__ ei,
                       const int* __restrict__ batch) {
    int i = blockIdx.x * blockDim.x + threadIdx.x;
    if (i < EE) atomicAdd(&g_cnt[ei[EE + i]], 1);
    if (i < NN) atomicAdd(&g_gcnt[batch[i]], 1);
}

// single-pass scan: blocks 0..249 scan g_cnt tiles (aggregate-only lookback,
// g_dis computed inline); block 250 scans g_gcnt -> g_goff.
__global__ void __launch_bounds__(256) k_scanall() {
    __shared__ int sh[256];
    int b = blockIdx.x, t = threadIdx.x;
    if (b < SCAN_B) {
        int lo = b * SCAN_R;
        // round A: elements [lo, lo+256)
        int cA = g_cnt[lo + t];
        g_dis[lo + t] = rsqrtf((float)(cA + 1));
        sh[t] = cA; __syncthreads();
        for (int off = 1; off < 256; off <<= 1) {
            int u = (t >= off) ? sh[t - off] : 0;
            __syncthreads(); sh[t] += u; __syncthreads();
        }
        int incA = sh[t];
        int carry = sh[255];
        __syncthreads();
        // round B: elements [lo+256, lo+400)
        int cB = 0;
        if (t < SCAN_R - 256) {
            cB = g_cnt[lo + 256 + t];
            g_dis[lo + 256 + t] = rsqrtf((float)(cB + 1));
        }
        sh[t] = cB; __syncthreads();
        for (int off = 1; off < 256; off <<= 1) {
            int u = (t >= off) ? sh[t - off] : 0;
            __syncthreads(); sh[t] += u; __syncthreads();
        }
        int incB = sh[t];
        int total = carry + sh[255];
        __syncthreads();
        // publish aggregate
        if (t == 0) {
            g_aggr[b] = total;
            __threadfence();
            ((volatile int*)g_flag)[b] = 1;
        }
        // lookback: sum aggregates of all predecessors (no serial chain)
        int part = 0;
        if (t < b) {
            while (((volatile int*)g_flag)[t] == 0) {}
            __threadfence();
            part = g_aggr[t];
        }
        sh[t] = part; __syncthreads();
        for (int off = 128; off > 0; off >>= 1) {
            if (t < off) sh[t] += sh[t + off];
            __syncthreads();
        }
        int base = sh[0];
        int ex0 = base + incA - cA;
        g_ptr[lo + t] = ex0;
        g_wp[lo + t]  = ex0;
        if (t < SCAN_R - 256) {
            int ex1 = base + carry + incB - cB;
            g_ptr[lo + 256 + t] = ex1;
            g_wp[lo + 256 + t]  = ex1;
        }
        if (b == SCAN_B - 1 && t == 0) g_ptr[NN] = EE;
    } else {
        // block 250: exclusive scan of g_gcnt (1000) -> g_goff
        int carry = 0;
        for (int base = 0; base < GG; base += 256) {
            int idx = base + t;
            int v = (idx < GG) ? g_gcnt[idx] : 0;
            sh[t] = v; __syncthreads();
            for (int off = 1; off < 256; off <<= 1) {
                int u = (t >= off) ? sh[t - off] : 0;
                __syncthreads(); sh[t] += u; __syncthreads();
            }
            if (idx < GG) g_goff[idx] = carry + sh[t] - v;
            carry += sh[255];
            __syncthreads();
        }
        if (t == 0) g_goff[GG] = NN;
    }
}

__global__ void k_scatter(const int* __restrict__ ei) {
    int i = blockIdx.x * blockDim.x + threadIdx.x;
    if (i >= EE) return;
    int s = ei[i];
    int d = ei[EE + i];
    int pos = atomicAdd(&g_wp[d], 1);
    int2 p;
    p.x = s;
    p.y = __float_as_int(g_dis[s] * g_dis[d]);
    g_epack[pos] = p;
}

// ---------------- layer 1 fused: agg(x) then @W1+b1, BN stats, affine tail --
// 32 nodes per block: phase 1 aggregates 7-dim x (8 lanes/node) into smem,
// phase 2 GEMMs from smem (8 threads/node x 8 cols), writes fp16 h.
__global__ void __launch_bounds__(256) k_l1(const float* __restrict__ x,
                                            const float* __restrict__ W1,
                                            const float* __restrict__ b1,
                                            const float* __restrict__ gamma,
                                            const float* __restrict__ beta) {
    __shared__ float Ws[FIN * HH];
    __shared__ float bs[HH];
    __shared__ float sax[32][8];
    __shared__ float s_h[32][HH];       // 8 KB
    __shared__ int s_last;
    int t = threadIdx.x;
    for (int j = t; j < FIN * HH; j += 256) Ws[j] = W1[j];
    if (t < HH) bs[t] = b1[t];
    int nl = t >> 3;                    // 0..31
    int sl = t & 7;
    int node = blockIdx.x * 32 + nl;    // NN % 32 == 0 -> always valid
    {
        float di = g_dis[node];
        float xv = (sl < FIN) ? x[node * FIN + sl] : 0.f;
        float acc = xv * di * di;       // self loop, norm = 1/deg
        int e0 = g_ptr[node], e1 = g_ptr[node + 1];
        for (int e = e0; e < e1; e++) {
            int2 ep = g_epack[e];
            float w = __int_as_float(ep.y);
            float v = (sl < FIN) ? x[ep.x * FIN + sl] : 0.f;
            acc = fmaf(w, v, acc);
        }
        sax[nl][sl] = acc;
    }
    __syncthreads();
    {
        int cg = sl;                    // 8 cols per thread
        float a[FIN];
#pragma unroll
        for (int k = 0; k < FIN; k++) a[k] = sax[nl][k];
        float acc[8];
#pragma unroll
        for (int j = 0; j < 8; j++) acc[j] = bs[cg * 8 + j];
#pragma unroll
        for (int k = 0; k < FIN; k++) {
            float hk = a[k];
            const float* wr = &Ws[k * HH + cg * 8];
#pragma unroll
            for (int j = 0; j < 8; j++) acc[j] = fmaf(hk, wr[j], acc[j]);
        }
        __half2* dst = (__half2*)(g_h16 + (size_t)node * HH) + cg * 4;
#pragma unroll
        for (int j = 0; j < 4; j++)
            dst[j] = __floats2half2_rn(acc[2 * j], acc[2 * j + 1]);
#pragma unroll
        for (int j = 0; j < 8; j++) s_h[nl][cg * 8 + j] = acc[j];
    }
    __syncthreads();
    if (t < 128) {
        int w = t >> 6, col = t & 63;
        float s = 0.f;
        if (w == 0) {
#pragma unroll
            for (int r = 0; r < 32; r++) s += s_h[r][col];
            atomicAdd(&g_bnsum[col], s);
        } else {
#pragma unroll
            for (int r = 0; r < 32; r++) { float v = s_h[r][col]; s = fmaf(v, v, s); }
            atomicAdd(&g_bnsq[col], s);
        }
    }
    // last-block affine tail
    __syncthreads();
    if (t == 0) {
        __threadfence();
        int done = atomicAdd(&g_ctr1, 1);
        s_last = (done == gridDim.x - 1);
    }
    __syncthreads();
    if (s_last) {
        if (t < HH) {
            __threadfence();
            float mean = g_bnsum[t] * (1.f / (float)NN);
            float var  = g_bnsq[t] * (1.f / (float)NN) - mean * mean;
            float a = gamma[t] * rsqrtf(var + 1e-5f);
            g_aff_a[t] = a;
            g_aff_c[t] = beta[t] - mean * a;
            g_bnsum[t] = 0.f;
            g_bnsq[t]  = 0.f;
        }
        if (t == 0) g_ctr1 = 0;
    }
}

// ---------------- H=64 aggregation: g_agg = A_norm @ relu(bn(h16)) ----------
// warp per node, lane owns 2 columns (half2 load), 2-edge unroll for MLP
__global__ void __launch_bounds__(256) k_agg() {
    int node = blockIdx.x * 8 + (threadIdx.x >> 5);
    int lane = threadIdx.x & 31;
    if (node >= NN) return;
    float a0 = g_aff_a[2 * lane],     a1 = g_aff_a[2 * lane + 1];
    float c0 = g_aff_c[2 * lane],     c1 = g_aff_c[2 * lane + 1];
    float di = g_dis[node];
    float invd = di * di;
    float2 hv = __half22float2(((const __half2*)(g_h16 + (size_t)node * HH))[lane]);
    float acc0 = fmaxf(fmaf(a0, hv.x, c0), 0.f) * invd;
    float acc1 = fmaxf(fmaf(a1, hv.y, c1), 0.f) * invd;
    int e0 = g_ptr[node], e1 = g_ptr[node + 1];
    int e = e0;
    for (; e + 2 <= e1; e += 2) {
        int2 ea = g_epack[e];
        int2 eb = g_epack[e + 1];
        float w0 = __int_as_float(ea.y);
        float w1 = __int_as_float(eb.y);
        float2 p = __half22float2(((const __half2*)(g_h16 + (size_t)ea.x * HH))[lane]);
        float2 q = __half22float2(((const __half2*)(g_h16 + (size_t)eb.x * HH))[lane]);
        acc0 = fmaf(w0, fmaxf(fmaf(a0, p.x, c0), 0.f), acc0);
        acc1 = fmaf(w0, fmaxf(fmaf(a1, p.y, c1), 0.f), acc1);
        acc0 = fmaf(w1, fmaxf(fmaf(a0, q.x, c0), 0.f), acc0);
        acc1 = fmaf(w1, fmaxf(fmaf(a1, q.y, c1), 0.f), acc1);
    }
    if (e < e1) {
        int2 ea = g_epack[e];
        float w0 = __int_as_float(ea.y);
        float2 p = __half22float2(((const __half2*)(g_h16 + (size_t)ea.x * HH))[lane]);
        acc0 = fmaf(w0, fmaxf(fmaf(a0, p.x, c0), 0.f), acc0);
        acc1 = fmaf(w0, fmaxf(fmaf(a1, p.y, c1), 0.f), acc1);
    }
    ((float2*)(g_agg + (size_t)node * HH))[lane] = make_float2(acc0, acc1);
}

// ---------------- h16 = g_agg @ W + b (N x 64 @ 64 x 64), 128 rows/block ----
// f32x2 packed FMA over row pairs; BN stats + last-block affine tail
__global__ void __launch_bounds__(256) k_gemm64(const float* __restrict__ W,
                                                const float* __restrict__ b,
                                                const float* __restrict__ gamma,
                                                const float* __restrict__ beta) {
    __shared__ float4 Ws[64 * 16];    // 16 KB  [k][cg]
    __shared__ float2 hs2[64 * 64];   // 32 KB  [k][rowpair]
    __shared__ int s_last;
    int t = threadIdx.x;
    int nb = blockIdx.x * 128;
    for (int j = t; j < 1024; j += 256) Ws[j] = ((const float4*)W)[j];
    {
        int rp = t & 63;              // row pair 0..63
        int kq = t >> 6;              // 0..3
        int r0 = nb + 2 * rp, r1 = r0 + 1;
        const float4* src = (const float4*)g_agg;
#pragma unroll
        for (int c = 0; c < 4; c++) {
            int k4 = kq * 4 + c;      // 0..15
            float4 va = (r0 < NN) ? src[(size_t)r0 * 16 + k4] : make_float4(0.f, 0.f, 0.f, 0.f);
            float4 vb = (r1 < NN) ? src[(size_t)r1 * 16 + k4] : make_float4(0.f, 0.f, 0.f, 0.f);
            hs2[(k4 * 4 + 0) * 64 + rp] = make_float2(va.x, vb.x);
            hs2[(k4 * 4 + 1) * 64 + rp] = make_float2(va.y, vb.y);
            hs2[(k4 * 4 + 2) * 64 + rp] = make_float2(va.z, vb.z);
            hs2[(k4 * 4 + 3) * 64 + rp] = make_float2(va.w, vb.w);
        }
    }
    __syncthreads();
    int cg  = t & 15;     // col group (4 cols)
    int rpg = t >> 4;     // row-pair group (4 pairs = 8 rows)
    float4 bias = ((const float4*)b)[cg];
    unsigned long long accp[4][4];
#pragma unroll
    for (int p = 0; p < 4; p++) {
        accp[p][0] = pack2(bias.x, bias.x);
        accp[p][1] = pack2(bias.y, bias.y);
        accp[p][2] = pack2(bias.z, bias.z);
        accp[p][3] = pack2(bias.w, bias.w);
    }
#pragma unroll 4
    for (int k = 0; k < 64; k++) {
        float4 w = Ws[k * 16 + cg];
        unsigned long long wx = pack2(w.x, w.x);
        unsigned long long wy = pack2(w.y, w.y);
        unsigned long long wz = pack2(w.z, w.z);
        unsigned long long ww = pack2(w.w, w.w);
#pragma unroll
        for (int p = 0; p < 4; p++) {
            float2 hp = hs2[k * 64 + rpg * 4 + p];
            unsigned long long h2 = pack2(hp.x, hp.y);
            accp[p][0] = fma2(h2, wx, accp[p][0]);
            accp[p][1] = fma2(h2, wy, accp[p][1]);
            accp[p][2] = fma2(h2, wz, accp[p][2]);
            accp[p][3] = fma2(h2, ww, accp[p][3]);
        }
    }
    float4 s4 = make_float4(0.f, 0.f, 0.f, 0.f);
    float4 q4 = make_float4(0.f, 0.f, 0.f, 0.f);
#pragma unroll
    for (int p = 0; p < 4; p++) {
        float2 c0 = unpack2(accp[p][0]);
        float2 c1 = unpack2(accp[p][1]);
        float2 c2 = unpack2(accp[p][2]);
        float2 c3 = unpack2(accp[p][3]);
        int r0 = nb + (rpg * 4 + p) * 2;
        int r1 = r0 + 1;
        if (r0 < NN) {
            __half2* dst = (__half2*)(g_h16 + (size_t)r0 * HH);
            dst[cg * 2]     = __floats2half2_rn(c0.x, c1.x);
            dst[cg * 2 + 1] = __floats2half2_rn(c2.x, c3.x);
            s4.x += c0.x; s4.y += c1.x; s4.z += c2.x; s4.w += c3.x;
            q4.x = fmaf(c0.x, c0.x, q4.x); q4.y = fmaf(c1.x, c1.x, q4.y);
            q4.z = fmaf(c2.x, c2.x, q4.z); q4.w = fmaf(c3.x, c3.x, q4.w);
        }
        if (r1 < NN) {
            __half2* dst = (__half2*)(g_h16 + (size_t)r1 * HH);
            dst[cg * 2]     = __floats2half2_rn(c0.y, c1.y);
            dst[cg * 2 + 1] = __floats2half2_rn(c2.y, c3.y);
            s4.x += c0.y; s4.y += c1.y; s4.z += c2.y; s4.w += c3.y;
            q4.x = fmaf(c0.y, c0.y, q4.x); q4.y = fmaf(c1.y, c1.y, q4.y);
            q4.z = fmaf(c2.y, c2.y, q4.z); q4.w = fmaf(c3.y, c3.y, q4.w);
        }
    }
    __syncthreads();
    float4* red = (float4*)Ws;    // reuse W smem (needs 512 float4, has 1024)
    red[(t >> 4) * 16 + cg]       = s4;
    red[256 + (t >> 4) * 16 + cg] = q4;
    __syncthreads();
    if (t < 32) {
        int which = t >> 4, col = t & 15;
        float4 s = make_float4(0.f, 0.f, 0.f, 0.f);
#pragma unroll
        for (int r = 0; r < 16; r++) {
            float4 v = red[which * 256 + r * 16 + col];
            s.x += v.x; s.y += v.y; s.z += v.z; s.w += v.w;
        }
        float* dst = which ? g_bnsq : g_bnsum;
        atomicAdd(&dst[col * 4 + 0], s.x);
        atomicAdd(&dst[col * 4 + 1], s.y);
        atomicAdd(&dst[col * 4 + 2], s.z);
        atomicAdd(&dst[col * 4 + 3], s.w);
    }
    // last-block affine tail
    __syncthreads();
    if (t == 0) {
        __threadfence();
        int done = atomicAdd(&g_ctr2, 1);
        s_last = (done == gridDim.x - 1);
    }
    __syncthreads();
    if (s_last) {
        if (t < HH) {
            __threadfence();
            float mean = g_bnsum[t] * (1.f / (float)NN);
            float var  = g_bnsq[t] * (1.f / (float)NN) - mean * mean;
            float a = gamma[t] * rsqrtf(var + 1e-5f);
            g_aff_a[t] = a;
            g_aff_c[t] = beta[t] - mean * a;
            g_bnsum[t] = 0.f;
            g_bnsq[t]  = 0.f;
        }
        if (t == 0) g_ctr2 = 0;
    }
}

// ---------------- pooling (over g_agg) + folded W3 + head -------------------
// pooled_h3 = mean(agg) @ W3 + b3  (GEMM-pool commute: pooling is linear)
__global__ void __launch_bounds__(256) k_final(
        const float* __restrict__ gf,  const float* __restrict__ Wg,
        const float* __restrict__ bg,  const float* __restrict__ W3,
        const float* __restrict__ b3,  const float* __restrict__ Wp1,
        const float* __restrict__ bp1, const float* __restrict__ Wp2,
        const float* __restrict__ bp2, float* __restrict__ out) {
    int g = blockIdx.x, t = threadIdx.x;
    int col = t & 63, rg = t >> 6;
    __shared__ float part[4][64];
    __shared__ float pool[64];
    __shared__ float comb[96];
    __shared__ float ys[64];
    int r0 = g_goff[g], r1 = g_goff[g + 1];
    float s = 0.f;
    for (int r = r0 + rg; r < r1; r += 4) s += g_agg[(size_t)r * HH + col];
    part[rg][col] = s;
    __syncthreads();
    if (t < 64) {
        float tot = part[0][t] + part[1][t] + part[2][t] + part[3][t];
        float cntf = (float)(r1 - r0);
        pool[t] = tot / fmaxf(cntf, 1.f);
    } else if (t < 96) {
        int j = t - 64;
        float a = bg[j];
#pragma unroll
        for (int k = 0; k < GFD; k++) a = fmaf(gf[g * GFD + k], Wg[k * 32 + j], a);
        comb[64 + j] = fmaxf(a, 0.f);
    }
    __syncthreads();
    if (t < 64) {
        float y = b3[t];
#pragma unroll
        for (int k = 0; k < HH; k++) y = fmaf(pool[k], W3[k * HH + t], y);
        comb[t] = y;   // no activation on layer-3 output
    }
    __syncthreads();
    if (t < 64) {
        float y = bp1[t];
#pragma unroll
        for (int k = 0; k < 96; k++) y = fmaf(comb[k], Wp1[k * HH + t], y);
        ys[t] = fmaxf(y, 0.f);
    }
    __syncthreads();
    if (t < TT) {
        float o = bp2[t];
#pragma unroll
        for (int k = 0; k < HH; k++) o = fmaf(ys[k], Wp2[k * TT + t], o);
        out[g * TT + t] = o;
    }
}

// ---------------- launch ----------------------------------------------------
extern "C" void kernel_launch(void* const* d_in, const int* in_sizes, int n_in,
                              void* d_out, int out_size) {
    const float* x      = (const float*)d_in[0];
    const float* gfeat  = (const float*)d_in[1];
    const float* W1     = (const float*)d_in[2];
    const float* b1     = (const float*)d_in[3];
    const float* W2     = (const float*)d_in[4];
    const float* b2     = (const float*)d_in[5];
    const float* W3     = (const float*)d_in[6];
    const float* b3     = (const float*)d_in[7];
    const float* gamma1 = (const float*)d_in[8];
    const float* beta1  = (const float*)d_in[9];
    const float* gamma2 = (const float*)d_in[10];
    const float* beta2  = (const float*)d_in[11];
    const float* Wg     = (const float*)d_in[12];
    const float* bg     = (const float*)d_in[13];
    const float* Wp1    = (const float*)d_in[14];
    const float* bp1    = (const float*)d_in[15];
    const float* Wp2    = (const float*)d_in[16];
    const float* bp2    = (const float*)d_in[17];
    const int* ei       = (const int*)d_in[18];
    const int* batch    = (const int*)d_in[19];
    float* out = (float*)d_out;

    const int TB = 256;
    const int gridN = (NN + TB - 1) / TB;       // 391
    const int gridE = (EE + TB - 1) / TB;       // 4688
    const int gridG64 = (NN + 127) / 128;       // 782

    // preprocessing: degree + dis, CSR (single-pass scan), graph offsets
    k_init<<<gridN, TB>>>();
    k_hist<<<gridE, TB>>>(ei, batch);
    k_scanall<<<SCAN_B + 1, TB>>>();
    k_scatter<<<gridE, TB>>>(ei);

    // layer 1: fused aggregate(x) + GEMM + BN stats + affine
    k_l1<<<NN / 32, TB>>>(x, W1, b1, gamma1, beta1);

    // layer 2: gather with fused relu(bn(.)), then GEMM + BN stats + affine
    k_agg<<<NN / 8, TB>>>();
    k_gemm64<<<gridG64, TB>>>(W2, b2, gamma2, beta2);

    // layer 3: gather only; GEMM3 folded into k_final (pool-GEMM commute)
    k_agg<<<NN / 8, TB>>>();

    // pooling + folded W3 + MLP head
    k_final<<<GG, TB>>>(gfeat, Wg, bg, W3, b3, Wp1, bp1, Wp2, bp2, out);
}